// round 11
// baseline (speedup 1.0000x reference)
#include <cuda_runtime.h>
#include <cstdint>

// GCNStack: out = relu((A @ x) @ W1 + b1) @ W2 + b2   (FFMA2, conflict-free smem)
//   x:[B,N,64] f32, A COO (idx [2,E] int32/int64 autodetected), val f32
// CSR build + ONE persistent fused kernel (512 thr):
//   warps 8-15: gather y = A@x per 64-node tile -> XOR-swizzled smem (double buf)
//   warps 0-7 : GEMM1 (2x32/lane) -> bias/relu -> sH -> GEMM2 (2x8/lane) -> out
// Lane mapping makes A-loads 4-row-broadcast and W-loads 4-way replicated:
// every LDS moves <=128B of unique data -> smem no longer the bottleneck.

#define B_CONST 4
#define CIN     64
#define HDIM    256
#define COUT    64
#define MAXN    65536
#define MAXE    2000000
#define SCAN_CHUNK 2048
#define MAXBLK  (MAXN / SCAN_CHUNK)

typedef unsigned long long ull;

static __device__ int   g_is64;
static __device__ int   g_counts[MAXN];
static __device__ int   g_rowptr[MAXN + 1];
static __device__ int   g_cursor[MAXN];
static __device__ int   g_part[MAXBLK];
static __device__ int   g_partpre[MAXBLK];
static __device__ int   g_ecol[MAXE];
static __device__ float g_eval[MAXE];

// ================= CSR build (identical to R8) =================
__device__ __forceinline__ int idx_row(const void* A, int e, int E, int is64, int N) {
    int r = is64 ? (int)((const long long*)A)[e] : ((const int*)A)[e];
    return r < 0 ? 0 : (r >= N ? N - 1 : r);
}
__device__ __forceinline__ int idx_col(const void* A, int e, int E, int is64, int N) {
    int c = is64 ? (int)((const long long*)A)[(size_t)E + e] : ((const int*)A)[(size_t)E + e];
    return c < 0 ? 0 : (c >= N ? N - 1 : c);
}

__global__ void k_zero(const int* __restrict__ A32, int E, int n) {
    __shared__ int sbad;
    int t = threadIdx.x;
    int i = blockIdx.x * blockDim.x + t;
    if (i < n) g_counts[i] = 0;
    if (blockIdx.x == 0) {
        if (t == 0) sbad = 0;
        __syncthreads();
        int cnt = E < 128 ? E : 128;
        if (t < cnt && A32[2 * t + 1] != 0) sbad = 1;
        __syncthreads();
        if (t == 0) g_is64 = !sbad;
    }
}

__global__ void k_count(const void* __restrict__ A, int E, int N) {
    int e = blockIdx.x * blockDim.x + threadIdx.x;
    if (e < E) atomicAdd(&g_counts[idx_row(A, e, E, g_is64, N)], 1);
}

__global__ __launch_bounds__(256) void k_blocksum(int N) {
    __shared__ int wsum[8];
    int b = blockIdx.x, t = threadIdx.x;
    int base = b * SCAN_CHUNK + t * 8;
    int s = 0;
#pragma unroll
    for (int i = 0; i < 8; i++) { int id = base + i; s += (id < N) ? g_counts[id] : 0; }
#pragma unroll
    for (int o = 16; o > 0; o >>= 1) s += __shfl_down_sync(0xffffffffu, s, o);
    if ((t & 31) == 0) wsum[t >> 5] = s;
    __syncthreads();
    if (t == 0) {
        int tot = 0;
#pragma unroll
        for (int w = 0; w < 8; w++) tot += wsum[w];
        g_part[b] = tot;
    }
}

__global__ void k_scanpart(int nblocks, int E, int N) {
    int lane = threadIdx.x;
    int v = (lane < nblocks) ? g_part[lane] : 0;
    int incl = v;
#pragma unroll
    for (int o = 1; o < 32; o <<= 1) {
        int u = __shfl_up_sync(0xffffffffu, incl, o);
        if (lane >= o) incl += u;
    }
    if (lane < nblocks) g_partpre[lane] = incl - v;
    if (lane == 0) g_rowptr[N] = E;
}

__global__ __launch_bounds__(256) void k_blockscan(int N) {
    __shared__ int wsum[8];
    int b = blockIdx.x, t = threadIdx.x;
    int lane = t & 31, w = t >> 5;
    int base = b * SCAN_CHUNK + t * 8;
    int v[8];
    int s = 0;
#pragma unroll
    for (int i = 0; i < 8; i++) {
        int id = base + i;
        v[i] = (id < N) ? g_counts[id] : 0;
        s += v[i];
    }
    int incl = s;
#pragma unroll
    for (int o = 1; o < 32; o <<= 1) {
        int u = __shfl_up_sync(0xffffffffu, incl, o);
        if (lane >= o) incl += u;
    }
    if (lane == 31) wsum[w] = incl;
    __syncthreads();
    if (w == 0 && lane < 8) {
        int z = wsum[lane];
#pragma unroll
        for (int o = 1; o < 8; o <<= 1) {
            int u = __shfl_up_sync(0xffu, z, o);
            if (lane >= o) z += u;
        }
        wsum[lane] = z;
    }
    __syncthreads();
    int run = g_partpre[b] + (incl - s) + (w ? wsum[w - 1] : 0);
#pragma unroll
    for (int i = 0; i < 8; i++) {
        int id = base + i;
        if (id < N) { g_rowptr[id] = run; g_cursor[id] = run; run += v[i]; }
    }
}

__global__ void k_scatter(const void* __restrict__ A, const float* __restrict__ A_val,
                          int E, int N) {
    int e = blockIdx.x * blockDim.x + threadIdx.x;
    if (e >= E) return;
    int is64 = g_is64;
    int r = idx_row(A, e, E, is64, N);
    int p = atomicAdd(&g_cursor[r], 1);
    g_ecol[p] = idx_col(A, e, E, is64, N);
    g_eval[p] = A_val[e];
}

// ================= smem primitives =================
__device__ __forceinline__ ull ffma2(ull a, ull b, ull c) {
    ull d;
    asm("fma.rn.f32x2 %0, %1, %2, %3;" : "=l"(d) : "l"(a), "l"(b), "l"(c));
    return d;
}
__device__ __forceinline__ ull pk2(float x, float y) {
    ull r;
    asm("mov.b64 %0, {%1, %2};" : "=l"(r) : "f"(x), "f"(y));
    return r;
}
__device__ __forceinline__ float2 upk(ull v) {
    float2 r;
    asm("mov.b64 {%0, %1}, %2;" : "=f"(r.x), "=f"(r.y) : "l"(v));
    return r;
}
__device__ __forceinline__ ull lds64(uint32_t a) {
    ull v;
    asm volatile("ld.shared.b64 %0, [%1];" : "=l"(v) : "r"(a));
    return v;
}
__device__ __forceinline__ float4 lds128(uint32_t a) {
    float4 v;
    asm volatile("ld.shared.v4.f32 {%0,%1,%2,%3}, [%4];"
                 : "=f"(v.x), "=f"(v.y), "=f"(v.z), "=f"(v.w) : "r"(a));
    return v;
}
__device__ __forceinline__ void sts128(uint32_t a, float4 v) {
    asm volatile("st.shared.v4.f32 [%0], {%1,%2,%3,%4};"
                 :: "r"(a), "f"(v.x), "f"(v.y), "f"(v.z), "f"(v.w) : "memory");
}

// ---- smem layout (bytes) ----
// sW1: [k=64][n=256] f32 rows (1KB)        @ 0       (64KB)
// sW2: [k=256][n=64] f32 rows (256B)       @ 65536   (64KB)
// sH : [r=64] rows of 1KB, 64 chunks, XOR-swizzled chunk^=((r&3)<<2)  @131072 (64KB)
// sY : 2 bufs x [r=64] rows of 256B, 16 chunks, chunk^=((r&3)<<2)     @196608 (32KB)
// b1 @229376 (1KB), b2 @230400 (256B)
#define OFF_W1 0u
#define OFF_W2 65536u
#define OFF_H  131072u
#define OFF_Y  196608u
#define OFF_B1 229376u
#define OFF_B2 230400u
#define SMEM_FUSED 230656

// ================= fused gather + FFMA2 MLP =================
__global__ __launch_bounds__(512, 1) void k_fused(
    const float* __restrict__ x,
    const float* __restrict__ W1, const float* __restrict__ b1,
    const float* __restrict__ W2, const float* __restrict__ b2,
    float* __restrict__ out, int N)
{
    extern __shared__ float smf[];
    uint32_t sb;
    asm("{ .reg .u64 tt; cvta.to.shared.u64 tt, %1; cvt.u32.u64 %0, tt; }"
        : "=r"(sb) : "l"(smf));

    int t = threadIdx.x;
    int wd = t >> 5;
    int l = t & 31;
    bool isCompute = (wd < 8);

    int nT = (N + 63) >> 6;
    int total = nT * B_CONST;

    // -------- gather: y(tile) -> XOR-swizzled smem buf --------
    auto gather_tile = [&](int tile, int buf) {
        int gt = t - 256;
        int hw = gt >> 4, lh = gt & 15;
        int bI = tile & 3;
        int n0 = (tile >> 2) << 6;
        const float4* xb = (const float4*)x + (size_t)bI * N * 16 + lh;
        uint32_t yb = sb + OFF_Y + (uint32_t)buf * 16384u;
#pragma unroll
        for (int j = 0; j < 4; j++) {
            int r = hw * 4 + j;
            int node = n0 + r;
            float4 acc = make_float4(0.f, 0.f, 0.f, 0.f);
            if (node < N) {
                int beg = g_rowptr[node], end = g_rowptr[node + 1];
                int i = beg;
                for (; i + 4 <= end; i += 4) {
                    int   c0 = g_ecol[i],     c1 = g_ecol[i + 1];
                    int   c2 = g_ecol[i + 2], c3 = g_ecol[i + 3];
                    float v0 = g_eval[i],     v1 = g_eval[i + 1];
                    float v2 = g_eval[i + 2], v3 = g_eval[i + 3];
                    float4 p0 = xb[(size_t)c0 * 16], p1 = xb[(size_t)c1 * 16];
                    float4 p2 = xb[(size_t)c2 * 16], p3 = xb[(size_t)c3 * 16];
                    acc.x += v0 * p0.x; acc.y += v0 * p0.y; acc.z += v0 * p0.z; acc.w += v0 * p0.w;
                    acc.x += v1 * p1.x; acc.y += v1 * p1.y; acc.z += v1 * p1.z; acc.w += v1 * p1.w;
                    acc.x += v2 * p2.x; acc.y += v2 * p2.y; acc.z += v2 * p2.z; acc.w += v2 * p2.w;
                    acc.x += v3 * p3.x; acc.y += v3 * p3.y; acc.z += v3 * p3.z; acc.w += v3 * p3.w;
                }
                for (; i < end; i++) {
                    int c = g_ecol[i]; float v = g_eval[i];
                    float4 p = xb[(size_t)c * 16];
                    acc.x += v * p.x; acc.y += v * p.y; acc.z += v * p.z; acc.w += v * p.w;
                }
            }
            uint32_t chunk = (uint32_t)lh ^ ((uint32_t)(r & 3) << 2);
            sts128(yb + (uint32_t)r * 256u + (chunk << 4), acc);
        }
    };

    // -------- prologue --------
    if (isCompute) {
        for (int i = t; i < 64 * 256 / 4; i += 256)
            ((float4*)smf)[i] = ((const float4*)W1)[i];                 // sW1
        for (int i = t; i < 256 * 64 / 4; i += 256)
            ((float4*)(smf + 16384))[i] = ((const float4*)W2)[i];       // sW2
        if (t < HDIM) smf[OFF_B1 / 4 + t] = b1[t];
        if (t < COUT) smf[OFF_B2 / 4 + t] = b2[t];
    } else {
        if ((int)blockIdx.x < total) gather_tile(blockIdx.x, 0);
    }
    __syncthreads();

    // compute-thread constants
    int l8 = l & 7, l3 = l >> 3;
    int r0 = 8 * wd + l3;                       // rows r0, r0+4
    uint32_t xr = (uint32_t)l3 << 2;            // chunk rotation
    uint32_t w1base = sb + OFF_W1 + 32u * (uint32_t)l8;  // + k*1024 + 256*j + 8m
    uint32_t w2base = sb + OFF_W2 + 32u * (uint32_t)l8;  // + k*256 + 8m
    uint32_t h0base = sb + OFF_H + (uint32_t)r0 * 1024u;
    uint32_t h1base = h0base + 4096u;
    uint32_t b1base = sb + OFF_B1 + 32u * (uint32_t)l8;  // + 256*j + 8m
    uint32_t b2base = sb + OFF_B2 + 32u * (uint32_t)l8;

    int buf = 0;
    for (int tile = blockIdx.x; tile < total; tile += gridDim.x, buf ^= 1) {
        if (isCompute) {
            int bI = tile & 3;
            int n0 = (tile >> 2) << 6;
            uint32_t y0 = sb + OFF_Y + (uint32_t)buf * 16384u + (uint32_t)r0 * 256u;
            uint32_t y1 = y0 + 1024u;

            // ---- GEMM1: h[64,256] = y @ W1; lane = 2 rows x 32 cols ----
            ull acc[2][4][4];
#pragma unroll
            for (int rr = 0; rr < 2; rr++)
#pragma unroll
                for (int j = 0; j < 4; j++)
#pragma unroll
                    for (int m = 0; m < 4; m++) acc[rr][j][m] = 0ull;

#pragma unroll 4
            for (int k4 = 0; k4 < 16; k4++) {
                uint32_t sw = (((uint32_t)k4 ^ xr) << 4);
                float4 af0 = lds128(y0 + sw);
                float4 af1 = lds128(y1 + sw);
                const float* a0p = (const float*)&af0;
                const float* a1p = (const float*)&af1;
#pragma unroll
                for (int kk = 0; kk < 4; kk++) {
                    uint32_t wb = w1base + (uint32_t)(k4 * 4 + kk) * 1024u;
                    ull aa0 = pk2(a0p[kk], a0p[kk]);
                    ull aa1 = pk2(a1p[kk], a1p[kk]);
#pragma unroll
                    for (int j = 0; j < 4; j++) {
                        uint32_t wj = wb + (uint32_t)j * 256u;
                        ull w0 = lds64(wj);
                        ull w1v = lds64(wj + 8u);
                        ull w2v = lds64(wj + 16u);
                        ull w3 = lds64(wj + 24u);
                        acc[0][j][0] = ffma2(aa0, w0,  acc[0][j][0]);
                        acc[0][j][1] = ffma2(aa0, w1v, acc[0][j][1]);
                        acc[0][j][2] = ffma2(aa0, w2v, acc[0][j][2]);
                        acc[0][j][3] = ffma2(aa0, w3,  acc[0][j][3]);
                        acc[1][j][0] = ffma2(aa1, w0,  acc[1][j][0]);
                        acc[1][j][1] = ffma2(aa1, w1v, acc[1][j][1]);
                        acc[1][j][2] = ffma2(aa1, w2v, acc[1][j][2]);
                        acc[1][j][3] = ffma2(aa1, w3,  acc[1][j][3]);
                    }
                }
            }

            // ---- epi1: bias + relu -> sH (swizzled) ----
#pragma unroll
            for (int j = 0; j < 4; j++) {
                uint32_t bj = b1base + (uint32_t)j * 256u;
                float2 bb0 = upk(lds64(bj));
                float2 bb1 = upk(lds64(bj + 8u));
                float2 bb2 = upk(lds64(bj + 16u));
                float2 bb3 = upk(lds64(bj + 24u));
                uint32_t c16 = (uint32_t)(16 * j + 2 * l8);
                uint32_t soff = ((c16 ^ xr) << 4);
#pragma unroll
                for (int rr = 0; rr < 2; rr++) {
                    float2 p0 = upk(acc[rr][j][0]);
                    float2 p1 = upk(acc[rr][j][1]);
                    float2 p2 = upk(acc[rr][j][2]);
                    float2 p3 = upk(acc[rr][j][3]);
                    float4 hA, hB;
                    hA.x = fmaxf(p0.x + bb0.x, 0.f);
                    hA.y = fmaxf(p0.y + bb0.y, 0.f);
                    hA.z = fmaxf(p1.x + bb1.x, 0.f);
                    hA.w = fmaxf(p1.y + bb1.y, 0.f);
                    hB.x = fmaxf(p2.x + bb2.x, 0.f);
                    hB.y = fmaxf(p2.y + bb2.y, 0.f);
                    hB.z = fmaxf(p3.x + bb3.x, 0.f);
                    hB.w = fmaxf(p3.y + bb3.y, 0.f);
                    uint32_t base = rr ? h1base : h0base;
                    sts128(base + soff, hA);
                    sts128(base + soff + 16u, hB);
                }
            }
            asm volatile("bar.sync 1, 256;" ::: "memory");   // compute warps only

            // ---- GEMM2: out[64,64] = h @ W2; lane = 2 rows x 8 cols ----
            ull c2[2][4];
#pragma unroll
            for (int rr = 0; rr < 2; rr++)
#pragma unroll
                for (int m = 0; m < 4; m++) c2[rr][m] = 0ull;

#pragma unroll 4
            for (int k4 = 0; k4 < 64; k4++) {
                uint32_t sw = (((uint32_t)k4 ^ xr) << 4);
                float4 af0 = lds128(h0base + sw);
                float4 af1 = lds128(h1base + sw);
                const float* a0p = (const float*)&af0;
                const float* a1p = (const float*)&af1;
#pragma unroll
                for (int kk = 0; kk < 4; kk++) {
                    uint32_t wb = w2base + (uint32_t)(k4 * 4 + kk) * 256u;
                    ull aa0 = pk2(a0p[kk], a0p[kk]);
                    ull aa1 = pk2(a1p[kk], a1p[kk]);
                    ull w0 = lds64(wb);
                    ull w1v = lds64(wb + 8u);
                    ull w2v = lds64(wb + 16u);
                    ull w3 = lds64(wb + 24u);
                    c2[0][0] = ffma2(aa0, w0,  c2[0][0]);
                    c2[0][1] = ffma2(aa0, w1v, c2[0][1]);
                    c2[0][2] = ffma2(aa0, w2v, c2[0][2]);
                    c2[0][3] = ffma2(aa0, w3,  c2[0][3]);
                    c2[1][0] = ffma2(aa1, w0,  c2[1][0]);
                    c2[1][1] = ffma2(aa1, w1v, c2[1][1]);
                    c2[1][2] = ffma2(aa1, w2v, c2[1][2]);
                    c2[1][3] = ffma2(aa1, w3,  c2[1][3]);
                }
            }

            // ---- epi2: bias -> out ----
            {
                float2 bb0 = upk(lds64(b2base));
                float2 bb1 = upk(lds64(b2base + 8u));
                float2 bb2 = upk(lds64(b2base + 16u));
                float2 bb3 = upk(lds64(b2base + 24u));
#pragma unroll
                for (int rr = 0; rr < 2; rr++) {
                    int row = n0 + r0 + rr * 4;
                    if (row < N) {
                        float2 p0 = upk(c2[rr][0]);
                        float2 p1 = upk(c2[rr][1]);
                        float2 p2 = upk(c2[rr][2]);
                        float2 p3 = upk(c2[rr][3]);
                        float4 oA = make_float4(p0.x + bb0.x, p0.y + bb0.y,
                                                p1.x + bb1.x, p1.y + bb1.y);
                        float4 oB = make_float4(p2.x + bb2.x, p2.y + bb2.y,
                                                p3.x + bb3.x, p3.y + bb3.y);
                        float* op = out + ((size_t)bI * N + row) * COUT + 8 * l8;
                        ((float4*)op)[0] = oA;
                        ((float4*)op)[1] = oB;
                    }
                }
            }
        } else {
            int next = tile + gridDim.x;
            if (next < total) gather_tile(next, buf ^ 1);
        }
        __syncthreads();   // sY[buf] consumed; sY[buf^1] ready; sH safe
    }
}

// ================= launch =================
extern "C" void kernel_launch(void* const* d_in, const int* in_sizes, int n_in,
                              void* d_out, int out_size) {
    const float* x  = (const float*)d_in[0];
    const void*  A  = d_in[1];
    const float* Av = (const float*)d_in[2];
    const float* W1 = (const float*)d_in[3];
    const float* b1 = (const float*)d_in[4];
    const float* W2 = (const float*)d_in[5];
    const float* b2 = (const float*)d_in[6];
    float* out = (float*)d_out;

    int E = in_sizes[1] / 2;
    int N = in_sizes[0] / (B_CONST * CIN);
    int nb = (N + SCAN_CHUNK - 1) / SCAN_CHUNK;

    k_zero<<<(N + 255) / 256, 256>>>((const int*)A, E, N);
    k_count<<<(E + 255) / 256, 256>>>(A, E, N);
    k_blocksum<<<nb, 256>>>(N);
    k_scanpart<<<1, 32>>>(nb, E, N);
    k_blockscan<<<nb, 256>>>(N);
    k_scatter<<<(E + 255) / 256, 256>>>(A, Av, E, N);

    cudaFuncSetAttribute(k_fused, cudaFuncAttributeMaxDynamicSharedMemorySize, SMEM_FUSED);
    k_fused<<<148, 512, SMEM_FUSED>>>(x, W1, b1, W2, b2, out, N);
}

// round 12
// speedup vs baseline: 1.9858x; 1.9858x over previous
#include <cuda_runtime.h>
#include <cstdint>

// GCNStack: out = relu((A @ x) @ W1 + b1) @ W2 + b2   (K-packed FFMA2)
//   x:[B,N,64] f32, A COO (idx [2,E] int32/int64 autodetected), val f32
// CSR build + ONE persistent fused kernel (512 thr):
//   warps 8-15: gather y = A@x per 32-node tile -> smem (double buf)
//   warps 0-7 : GEMM1/GEMM2 with K-packed fma.rn.f32x2:
//     acc.lo accumulates even-k MACs, acc.hi odd-k; epilogue adds halves.
//   Both FFMA2 operands are natural 64-bit pairs loaded via ld.shared.b64
//   (y rows contiguous in k; W stored transposed [n][k] with lane-rotated
//   rows) -> zero packing MOVs, <=2-way smem conflicts.

#define B_CONST 4
#define CIN     64
#define HDIM    256
#define COUT    64
#define MAXN    65536
#define MAXE    2000000
#define SCAN_CHUNK 2048
#define MAXBLK  (MAXN / SCAN_CHUNK)

typedef unsigned long long ull;

static __device__ int   g_is64;
static __device__ int   g_counts[MAXN];
static __device__ int   g_rowptr[MAXN + 1];
static __device__ int   g_cursor[MAXN];
static __device__ int   g_part[MAXBLK];
static __device__ int   g_partpre[MAXBLK];
static __device__ int   g_ecol[MAXE];
static __device__ float g_eval[MAXE];

// ================= CSR build (identical to R8) =================
__device__ __forceinline__ int idx_row(const void* A, int e, int E, int is64, int N) {
    int r = is64 ? (int)((const long long*)A)[e] : ((const int*)A)[e];
    return r < 0 ? 0 : (r >= N ? N - 1 : r);
}
__device__ __forceinline__ int idx_col(const void* A, int e, int E, int is64, int N) {
    int c = is64 ? (int)((const long long*)A)[(size_t)E + e] : ((const int*)A)[(size_t)E + e];
    return c < 0 ? 0 : (c >= N ? N - 1 : c);
}

__global__ void k_zero(const int* __restrict__ A32, int E, int n) {
    __shared__ int sbad;
    int t = threadIdx.x;
    int i = blockIdx.x * blockDim.x + t;
    if (i < n) g_counts[i] = 0;
    if (blockIdx.x == 0) {
        if (t == 0) sbad = 0;
        __syncthreads();
        int cnt = E < 128 ? E : 128;
        if (t < cnt && A32[2 * t + 1] != 0) sbad = 1;
        __syncthreads();
        if (t == 0) g_is64 = !sbad;
    }
}

__global__ void k_count(const void* __restrict__ A, int E, int N) {
    int e = blockIdx.x * blockDim.x + threadIdx.x;
    if (e < E) atomicAdd(&g_counts[idx_row(A, e, E, g_is64, N)], 1);
}

__global__ __launch_bounds__(256) void k_blocksum(int N) {
    __shared__ int wsum[8];
    int b = blockIdx.x, t = threadIdx.x;
    int base = b * SCAN_CHUNK + t * 8;
    int s = 0;
#pragma unroll
    for (int i = 0; i < 8; i++) { int id = base + i; s += (id < N) ? g_counts[id] : 0; }
#pragma unroll
    for (int o = 16; o > 0; o >>= 1) s += __shfl_down_sync(0xffffffffu, s, o);
    if ((t & 31) == 0) wsum[t >> 5] = s;
    __syncthreads();
    if (t == 0) {
        int tot = 0;
#pragma unroll
        for (int w = 0; w < 8; w++) tot += wsum[w];
        g_part[b] = tot;
    }
}

__global__ void k_scanpart(int nblocks, int E, int N) {
    int lane = threadIdx.x;
    int v = (lane < nblocks) ? g_part[lane] : 0;
    int incl = v;
#pragma unroll
    for (int o = 1; o < 32; o <<= 1) {
        int u = __shfl_up_sync(0xffffffffu, incl, o);
        if (lane >= o) incl += u;
    }
    if (lane < nblocks) g_partpre[lane] = incl - v;
    if (lane == 0) g_rowptr[N] = E;
}

__global__ __launch_bounds__(256) void k_blockscan(int N) {
    __shared__ int wsum[8];
    int b = blockIdx.x, t = threadIdx.x;
    int lane = t & 31, w = t >> 5;
    int base = b * SCAN_CHUNK + t * 8;
    int v[8];
    int s = 0;
#pragma unroll
    for (int i = 0; i < 8; i++) {
        int id = base + i;
        v[i] = (id < N) ? g_counts[id] : 0;
        s += v[i];
    }
    int incl = s;
#pragma unroll
    for (int o = 1; o < 32; o <<= 1) {
        int u = __shfl_up_sync(0xffffffffu, incl, o);
        if (lane >= o) incl += u;
    }
    if (lane == 31) wsum[w] = incl;
    __syncthreads();
    if (w == 0 && lane < 8) {
        int z = wsum[lane];
#pragma unroll
        for (int o = 1; o < 8; o <<= 1) {
            int u = __shfl_up_sync(0xffu, z, o);
            if (lane >= o) z += u;
        }
        wsum[lane] = z;
    }
    __syncthreads();
    int run = g_partpre[b] + (incl - s) + (w ? wsum[w - 1] : 0);
#pragma unroll
    for (int i = 0; i < 8; i++) {
        int id = base + i;
        if (id < N) { g_rowptr[id] = run; g_cursor[id] = run; run += v[i]; }
    }
}

__global__ void k_scatter(const void* __restrict__ A, const float* __restrict__ A_val,
                          int E, int N) {
    int e = blockIdx.x * blockDim.x + threadIdx.x;
    if (e >= E) return;
    int is64 = g_is64;
    int r = idx_row(A, e, E, is64, N);
    int p = atomicAdd(&g_cursor[r], 1);
    g_ecol[p] = idx_col(A, e, E, is64, N);
    g_eval[p] = A_val[e];
}

// ================= primitives =================
__device__ __forceinline__ ull ffma2(ull a, ull b, ull c) {
    ull d;
    asm("fma.rn.f32x2 %0, %1, %2, %3;" : "=l"(d) : "l"(a), "l"(b), "l"(c));
    return d;
}
__device__ __forceinline__ float2 upk(ull v) {
    float2 r;
    asm("mov.b64 {%0, %1}, %2;" : "=f"(r.x), "=f"(r.y) : "l"(v));
    return r;
}
__device__ __forceinline__ ull lds64(uint32_t a) {
    ull v;
    asm volatile("ld.shared.b64 %0, [%1];" : "=l"(v) : "r"(a));
    return v;
}
__device__ __forceinline__ void sts32(uint32_t a, float v) {
    asm volatile("st.shared.f32 [%0], %1;" :: "r"(a), "f"(v) : "memory");
}
__device__ __forceinline__ void sts128(uint32_t a, float4 v) {
    asm volatile("st.shared.v4.f32 [%0], {%1,%2,%3,%4};"
                 :: "r"(a), "f"(v.x), "f"(v.y), "f"(v.z), "f"(v.w) : "memory");
}

// ---- smem layout (bytes) ----
// W1T: [n=256][k=64] f32, 256B rows, row n k-rotated by (n&31) k2-units   (64KB)
// W2T: [n=64][k=256] f32, 1KB rows, row n k-rotated by (n&31) k2-units   (64KB)
// sH : [r=32][k=256] f32, 1KB linear rows                                 (32KB)
// sY : 2 bufs x [r=32][k=64] f32, 256B linear rows                        (16KB)
#define OFF_W1T 0u
#define OFF_W2T 65536u
#define OFF_H   131072u
#define OFF_Y   163840u
#define OFF_B1  180224u
#define OFF_B2  181248u
#define SMEM_FUSED 181504

// ================= fused gather + K-packed FFMA2 MLP =================
__global__ __launch_bounds__(512, 1) void k_fused(
    const float* __restrict__ x,
    const float* __restrict__ W1, const float* __restrict__ b1,
    const float* __restrict__ W2, const float* __restrict__ b2,
    float* __restrict__ out, int N)
{
    extern __shared__ float smf[];
    uint32_t sb;
    asm("{ .reg .u64 tt; cvta.to.shared.u64 tt, %1; cvt.u32.u64 %0, tt; }"
        : "=r"(sb) : "l"(smf));

    int t = threadIdx.x;
    int wd = t >> 5;
    int l = t & 31;
    bool isCompute = (wd < 8);

    int nT = (N + 31) >> 5;
    int total = nT * B_CONST;

    // -------- gather: y(tile) -> linear smem buf (32 rows x 256B) --------
    auto gather_tile = [&](int tile, int buf) {
        int gt = t - 256;
        int hw = gt >> 4, lh = gt & 15;
        int bI = tile & 3;
        int n0 = (tile >> 2) << 5;
        const float4* xb = (const float4*)x + (size_t)bI * N * 16 + lh;
        uint32_t yb = sb + OFF_Y + (uint32_t)buf * 8192u;
#pragma unroll
        for (int j = 0; j < 2; j++) {
            int r = hw * 2 + j;
            int node = n0 + r;
            float4 acc = make_float4(0.f, 0.f, 0.f, 0.f);
            if (node < N) {
                int beg = g_rowptr[node], end = g_rowptr[node + 1];
                int i = beg;
                for (; i + 4 <= end; i += 4) {
                    int   c0 = g_ecol[i],     c1 = g_ecol[i + 1];
                    int   c2 = g_ecol[i + 2], c3 = g_ecol[i + 3];
                    float v0 = g_eval[i],     v1 = g_eval[i + 1];
                    float v2 = g_eval[i + 2], v3 = g_eval[i + 3];
                    float4 p0 = xb[(size_t)c0 * 16], p1 = xb[(size_t)c1 * 16];
                    float4 p2 = xb[(size_t)c2 * 16], p3 = xb[(size_t)c3 * 16];
                    acc.x += v0 * p0.x; acc.y += v0 * p0.y; acc.z += v0 * p0.z; acc.w += v0 * p0.w;
                    acc.x += v1 * p1.x; acc.y += v1 * p1.y; acc.z += v1 * p1.z; acc.w += v1 * p1.w;
                    acc.x += v2 * p2.x; acc.y += v2 * p2.y; acc.z += v2 * p2.z; acc.w += v2 * p2.w;
                    acc.x += v3 * p3.x; acc.y += v3 * p3.y; acc.z += v3 * p3.z; acc.w += v3 * p3.w;
                }
                for (; i < end; i++) {
                    int c = g_ecol[i]; float v = g_eval[i];
                    float4 p = xb[(size_t)c * 16];
                    acc.x += v * p.x; acc.y += v * p.y; acc.z += v * p.z; acc.w += v * p.w;
                }
            }
            sts128(yb + (uint32_t)r * 256u + (uint32_t)lh * 16u, acc);
        }
    };

    // -------- prologue: transpose weights into rotated smem --------
    if (isCompute) {
        for (int i = t; i < 64 * 256; i += 256) {          // W1 [k][n] -> W1T [n][k]
            int k = i >> 8, n = i & 255;
            uint32_t off = (uint32_t)n * 256u
                         + (uint32_t)((((k >> 1) + (n & 31)) & 31) * 8 + (k & 1) * 4);
            *(float*)((char*)smf + OFF_W1T + off) = W1[i];
        }
        for (int i = t; i < 256 * 64; i += 256) {          // W2 [k][n] -> W2T [n][k]
            int k = i >> 6, n = i & 63;
            uint32_t off = (uint32_t)n * 1024u
                         + (uint32_t)((((k >> 1) + (n & 31)) & 127) * 8 + (k & 1) * 4);
            *(float*)((char*)smf + OFF_W2T + off) = W2[i];
        }
        if (t < HDIM) smf[OFF_B1 / 4 + t] = b1[t];
        if (t < COUT) smf[OFF_B2 / 4 + t] = b2[t];
    } else {
        if ((int)blockIdx.x < total) gather_tile(blockIdx.x, 0);
    }
    __syncthreads();

    // per-thread constants (compute warps): rows 4w..4w+3, GEMM1 cols l+32j,
    // GEMM2 cols l, l+32
    float b1r[8], b2r[2];
    if (isCompute) {
#pragma unroll
        for (int j = 0; j < 8; j++) b1r[j] = smf[OFF_B1 / 4 + l + 32 * j];
        b2r[0] = smf[OFF_B2 / 4 + l];
        b2r[1] = smf[OFF_B2 / 4 + l + 32];
    }
    uint32_t w1base = sb + OFF_W1T + (uint32_t)l * 256u;   // + j*8192 + rot
    uint32_t w2base = sb + OFF_W2T + (uint32_t)l * 1024u;  // + jj*32768 + rot
    uint32_t hbase  = sb + OFF_H + (uint32_t)(4 * wd) * 1024u;

    int buf = 0;
    for (int tile = blockIdx.x; tile < total; tile += gridDim.x, buf ^= 1) {
        if (isCompute) {
            int bI = tile & 3;
            int n0 = (tile >> 2) << 5;
            uint32_t ybase = sb + OFF_Y + (uint32_t)buf * 8192u
                           + (uint32_t)(4 * wd) * 256u;

            // ---- GEMM1: h[32,256] = y @ W1 (K-packed) ----
            ull acc[4][8];
#pragma unroll
            for (int i = 0; i < 4; i++)
#pragma unroll
                for (int j = 0; j < 8; j++) acc[i][j] = 0ull;

#pragma unroll 8
            for (int k2 = 0; k2 < 32; k2++) {
                ull a0 = lds64(ybase + (uint32_t)k2 * 8u);
                ull a1 = lds64(ybase + 256u + (uint32_t)k2 * 8u);
                ull a2 = lds64(ybase + 512u + (uint32_t)k2 * 8u);
                ull a3 = lds64(ybase + 768u + (uint32_t)k2 * 8u);
                uint32_t rot = (uint32_t)(((k2 + l) & 31) * 8);
                uint32_t wa = w1base + rot;
#pragma unroll
                for (int j = 0; j < 8; j++) {
                    ull wv = lds64(wa + (uint32_t)j * 8192u);
                    acc[0][j] = ffma2(a0, wv, acc[0][j]);
                    acc[1][j] = ffma2(a1, wv, acc[1][j]);
                    acc[2][j] = ffma2(a2, wv, acc[2][j]);
                    acc[3][j] = ffma2(a3, wv, acc[3][j]);
                }
            }

            // ---- epi1: horizontal add + bias + relu -> sH (linear) ----
#pragma unroll
            for (int i = 0; i < 4; i++) {
                uint32_t hrow = hbase + (uint32_t)i * 1024u + (uint32_t)l * 4u;
#pragma unroll
                for (int j = 0; j < 8; j++) {
                    float2 p = upk(acc[i][j]);
                    float h = fmaxf(p.x + p.y + b1r[j], 0.f);
                    sts32(hrow + (uint32_t)j * 128u, h);
                }
            }
            asm volatile("bar.sync 1, 256;" ::: "memory");  // compute warps only

            // ---- GEMM2: out[32,64] = h @ W2 (K-packed) ----
            ull c2[4][2];
#pragma unroll
            for (int i = 0; i < 4; i++) { c2[i][0] = 0ull; c2[i][1] = 0ull; }

#pragma unroll 8
            for (int k2 = 0; k2 < 128; k2++) {
                ull a0 = lds64(hbase + (uint32_t)k2 * 8u);
                ull a1 = lds64(hbase + 1024u + (uint32_t)k2 * 8u);
                ull a2 = lds64(hbase + 2048u + (uint32_t)k2 * 8u);
                ull a3 = lds64(hbase + 3072u + (uint32_t)k2 * 8u);
                uint32_t rot = (uint32_t)(((k2 + l) & 127) * 8);
                ull w0 = lds64(w2base + rot);
                ull w1v = lds64(w2base + 32768u + rot);
                c2[0][0] = ffma2(a0, w0,  c2[0][0]);
                c2[0][1] = ffma2(a0, w1v, c2[0][1]);
                c2[1][0] = ffma2(a1, w0,  c2[1][0]);
                c2[1][1] = ffma2(a1, w1v, c2[1][1]);
                c2[2][0] = ffma2(a2, w0,  c2[2][0]);
                c2[2][1] = ffma2(a2, w1v, c2[2][1]);
                c2[3][0] = ffma2(a3, w0,  c2[3][0]);
                c2[3][1] = ffma2(a3, w1v, c2[3][1]);
            }

            // ---- epi2: horizontal add + bias -> out ----
#pragma unroll
            for (int i = 0; i < 4; i++) {
                int row = n0 + 4 * wd + i;
                if (row < N) {
                    float2 p0 = upk(c2[i][0]);
                    float2 p1 = upk(c2[i][1]);
                    float* op = out + ((size_t)bI * N + row) * COUT;
                    op[l]      = p0.x + p0.y + b2r[0];
                    op[l + 32] = p1.x + p1.y + b2r[1];
                }
            }
        } else {
            int next = tile + gridDim.x;
            if (next < total) gather_tile(next, buf ^ 1);
        }
        __syncthreads();   // sY[buf] consumed; sY[buf^1] ready; sH safe
    }
}

// ================= launch =================
extern "C" void kernel_launch(void* const* d_in, const int* in_sizes, int n_in,
                              void* d_out, int out_size) {
    const float* x  = (const float*)d_in[0];
    const void*  A  = d_in[1];
    const float* Av = (const float*)d_in[2];
    const float* W1 = (const float*)d_in[3];
    const float* b1 = (const float*)d_in[4];
    const float* W2 = (const float*)d_in[5];
    const float* b2 = (const float*)d_in[6];
    float* out = (float*)d_out;

    int E = in_sizes[1] / 2;
    int N = in_sizes[0] / (B_CONST * CIN);
    int nb = (N + SCAN_CHUNK - 1) / SCAN_CHUNK;

    k_zero<<<(N + 255) / 256, 256>>>((const int*)A, E, N);
    k_count<<<(E + 255) / 256, 256>>>(A, E, N);
    k_blocksum<<<nb, 256>>>(N);
    k_scanpart<<<1, 32>>>(nb, E, N);
    k_blockscan<<<nb, 256>>>(N);
    k_scatter<<<(E + 255) / 256, 256>>>(A, Av, E, N);

    cudaFuncSetAttribute(k_fused, cudaFuncAttributeMaxDynamicSharedMemorySize, SMEM_FUSED);
    k_fused<<<148, 512, SMEM_FUSED>>>(x, W1, b1, W2, b2, out, N);
}